// round 16
// baseline (speedup 1.0000x reference)
#include <cuda_runtime.h>
#include <cuda_fp16.h>
#include <cstdint>

#define DIM    1024
#define BATCH  2
#define SEQ    2048
#define NHEADS 16
#define DH     64
#define TOKENS (BATCH*SEQ)      // 4096
#define QKV_N  (3*DIM)          // 3072
#define KDIM   1024

// ---------------- scratch (__device__ globals; allocation-free rule) --------
__device__ __align__(16) __half g_qh[BATCH*NHEADS*SEQ*DH]; // fp16 q (pre-scaled 0.125)
__device__ __align__(16) __half g_kh[BATCH*NHEADS*SEQ*DH]; // fp16 k
__device__ __align__(16) __half g_vh[BATCH*NHEADS*SEQ*DH]; // fp16 v

__device__ __align__(16) __half g_xh    [TOKENS*KDIM];     // x      fp16
__device__ __align__(16) __half g_oh    [TOKENS*DIM];      // attn O fp16 [b,n,c]
__device__ __align__(16) __half g_qkvwh [QKV_N*KDIM];      // qkv_w  fp16
__device__ __align__(16) __half g_projwh[DIM*KDIM];        // proj_w fp16

// ---------------------------------------------------------------------------
// PTX helpers (plain sm_80-era PTX; valid on compute_103)
// ---------------------------------------------------------------------------
__device__ __forceinline__ uint32_t smem_u32(const void* p) {
    uint32_t a;
    asm("{ .reg .u64 t; cvta.to.shared.u64 t, %1; cvt.u32.u64 %0, t; }"
        : "=r"(a) : "l"(p));
    return a;
}
__device__ __forceinline__ void cp16(uint32_t dst, const void* src) {
    asm volatile("cp.async.cg.shared.global [%0], [%1], 16;"
                 :: "r"(dst), "l"(src) : "memory");
}
#define CP_COMMIT() asm volatile("cp.async.commit_group;" ::: "memory")
#define CP_WAIT0()  asm volatile("cp.async.wait_group 0;"  ::: "memory")
#define CP_WAIT1()  asm volatile("cp.async.wait_group 1;"  ::: "memory")
#define CP_WAIT2()  asm volatile("cp.async.wait_group 2;"  ::: "memory")
#define CP_WAIT_STAGE(S, NS) do {                  \
    if      ((S) + 2 < (NS)) CP_WAIT2();           \
    else if ((S) + 1 < (NS)) CP_WAIT1();           \
    else                     CP_WAIT0();           \
} while (0)

__device__ __forceinline__ void ldsm4(uint32_t* r, uint32_t a) {
    asm volatile("ldmatrix.sync.aligned.m8n8.x4.shared.b16 {%0,%1,%2,%3}, [%4];"
                 : "=r"(r[0]), "=r"(r[1]), "=r"(r[2]), "=r"(r[3]) : "r"(a));
}
__device__ __forceinline__ void ldsm4t(uint32_t* r, uint32_t a) {
    asm volatile("ldmatrix.sync.aligned.m8n8.x4.trans.shared.b16 {%0,%1,%2,%3}, [%4];"
                 : "=r"(r[0]), "=r"(r[1]), "=r"(r[2]), "=r"(r[3]) : "r"(a));
}
__device__ __forceinline__ void mma_h(float* c, uint32_t a0, uint32_t a1,
                                      uint32_t a2, uint32_t a3,
                                      uint32_t b0, uint32_t b1) {
    asm volatile(
        "mma.sync.aligned.m16n8k16.row.col.f32.f16.f16.f32 "
        "{%0,%1,%2,%3}, {%4,%5,%6,%7}, {%8,%9}, {%0,%1,%2,%3};"
        : "+f"(c[0]), "+f"(c[1]), "+f"(c[2]), "+f"(c[3])
        : "r"(a0), "r"(a1), "r"(a2), "r"(a3), "r"(b0), "r"(b1));
}

// ---------------------------------------------------------------------------
// tofp16_all: one launch converting x, qkv_w, proj_w fp32->fp16
// ---------------------------------------------------------------------------
#define N0_4 (TOKENS*KDIM/4)
#define N1_4 (QKV_N*KDIM/4)
#define N2_4 (DIM*KDIM/4)
#define NALL4 (N0_4 + N1_4 + N2_4)

__global__ __launch_bounds__(256)
void tofp16_all(const float* __restrict__ x, const float* __restrict__ qw,
                const float* __restrict__ pw)
{
    int i = blockIdx.x*256 + threadIdx.x;
    const float* s; __half* d;
    if (i < N0_4)              { s = x;  d = g_xh;     }
    else if (i < N0_4 + N1_4)  { s = qw; d = g_qkvwh;  i -= N0_4; }
    else                       { s = pw; d = g_projwh; i -= N0_4 + N1_4; }
    float4 v = reinterpret_cast<const float4*>(s)[i];
    __half2 h01 = __floats2half2_rn(v.x, v.y);
    __half2 h23 = __floats2half2_rn(v.z, v.w);
    uint2 pk;
    pk.x = *reinterpret_cast<uint32_t*>(&h01);
    pk.y = *reinterpret_cast<uint32_t*>(&h23);
    reinterpret_cast<uint2*>(d)[i] = pk;
}

__device__ __forceinline__ void store_qkv_h(int m, int col, float x, float y) {
    const int c3 = col >> 10;
    const int h  = (col >> 6) & 15, d = col & 63;
    const int b  = m >> 11,  n = m & 2047;
    const float sc = (c3 == 0) ? 0.125f : 1.0f;
    __half* p = (c3 == 0) ? g_qh : (c3 == 1) ? g_kh : g_vh;
    *reinterpret_cast<__half2*>(
        &p[((size_t)((b << 4) + h)*SEQ + n)*DH + d]) =
        __floats2half2_rn(x*sc, y*sc);
}

// ---------------------------------------------------------------------------
// gemm_qkv (occupancy-3): CTA 128(M)x64(N), BK=32, 8 warps (4m x 2n),
// warp tile 32x32 -> acc 32 regs/thread -> 3 CTAs/SM (24 warps, 6/SMSP).
// 3-buffer cp.async ring, 2 stages in flight.
// FIX vs R14: full 64B row coverage — A 512 chunk-assignments (2/thread),
// B 256 (1/thread); previously bytes 32..63 of every row were never written
// (uninitialized smem -> NaN).
// ---------------------------------------------------------------------------
#define QARS   80                          // row stride bytes (64B data + 16)
#define QSTAGE ((128+64)*QARS)             // 15360
#define QSMEM  (3*QSTAGE)                  // 46080 -> 3 CTAs/SM
#define QNSTG  (KDIM/32)                   // 32

__global__ __launch_bounds__(256, 3)
void gemm_qkv(const __half* __restrict__ Ag, const __half* __restrict__ Wg,
              const float* __restrict__ bias)
{
    extern __shared__ char smem[];
    const uint32_t sbase = smem_u32(smem);
    const int tid  = threadIdx.x;
    const int lane = tid & 31, wid = tid >> 5;
    const int warp_m = wid >> 1, warp_n = wid & 1;
    const int m0 = blockIdx.y << 7, n0 = blockIdx.x << 6;

    // 16B chunks: each row has 4 (BK=32 halves = 64B).
    // A: rows arow, arow+64 (2 chunks/thread); B: row arow (1 chunk/thread).
    const int arow = tid >> 2, ak = tid & 3;

    const __half* Ab = Ag + (size_t)m0*KDIM;
    const __half* Wb = Wg + (size_t)n0*KDIM;

#define LOAD_STAGE(S, BUF) do {                                               \
    const uint32_t sa = sbase + (BUF)*QSTAGE;                                 \
    const uint32_t sw = sa + 128*QARS;                                        \
    const size_t ko = (size_t)(S)*32 + ak*8;                                  \
    cp16(sa + arow*QARS + ak*16,      Ab + (size_t)arow*KDIM + ko);           \
    cp16(sa + (arow+64)*QARS + ak*16, Ab + (size_t)(arow+64)*KDIM + ko);      \
    cp16(sw + arow*QARS + ak*16,      Wb + (size_t)arow*KDIM + ko);           \
} while (0)

    const uint32_t a_off = (uint32_t)((warp_m*32 + (lane & 15))*QARS
                                      + (lane >> 4)*16);
    const uint32_t b_off = (uint32_t)((warp_n*32 + (lane & 7)
                                      + ((lane >> 4) & 1)*8)*QARS
                                      + ((lane >> 3) & 1)*16);

    float acc[2][4][4] = {};

    LOAD_STAGE(0, 0); CP_COMMIT();
    LOAD_STAGE(1, 1); CP_COMMIT();

    for (int s = 0; s < QNSTG; ++s) {
        CP_WAIT1();                       // stage s resident
        __syncthreads();                  // buffer (s+2)%3 fully consumed
        if (s + 2 < QNSTG) LOAD_STAGE(s + 2, (s + 2) % 3);
        CP_COMMIT();

        const uint32_t ab = sbase + (s % 3)*QSTAGE;
        const uint32_t bb = ab + 128*QARS;
#pragma unroll
        for (int kk = 0; kk < 2; ++kk) {
            uint32_t bf[2][4];
            ldsm4(bf[0], bb + b_off + kk*32);
            ldsm4(bf[1], bb + b_off + 16*QARS + kk*32);
#pragma unroll
            for (int mt = 0; mt < 2; ++mt) {
                uint32_t af[4];
                ldsm4(af, ab + a_off + mt*16*QARS + kk*32);
#pragma unroll
                for (int nt = 0; nt < 4; ++nt)
                    mma_h(acc[mt][nt], af[0], af[1], af[2], af[3],
                          bf[nt >> 1][(nt & 1)*2],
                          bf[nt >> 1][(nt & 1)*2 + 1]);
            }
        }
    }
#undef LOAD_STAGE

    const int gr = lane >> 2, tg = lane & 3;
#pragma unroll
    for (int mt = 0; mt < 2; ++mt) {
        const int r0 = m0 + warp_m*32 + mt*16 + gr;
#pragma unroll
        for (int nt = 0; nt < 4; ++nt) {
            const int col = n0 + warp_n*32 + nt*8 + tg*2;
            const float2 bv = *reinterpret_cast<const float2*>(bias + col);
            store_qkv_h(r0,     col, acc[mt][nt][0] + bv.x,
                                     acc[mt][nt][1] + bv.y);
            store_qkv_h(r0 + 8, col, acc[mt][nt][2] + bv.x,
                                     acc[mt][nt][3] + bv.y);
        }
    }
}

// ---------------------------------------------------------------------------
// gemm_proj (R13-proven): BM=BN=128, BK=64, 8 warps, 3-buffer ring.
// ---------------------------------------------------------------------------
#define GARS       144
#define STAGE_OPER (128*GARS)
#define STAGE_B    (2*STAGE_OPER)          // 36864
#define GSMEM      (3*STAGE_B)             // 110592
#define NSTG       (KDIM/64)               // 16

__global__ __launch_bounds__(256, 2)
void gemm_proj(const __half* __restrict__ Ag, const __half* __restrict__ Wg,
               const float* __restrict__ bias, float* __restrict__ outp)
{
    extern __shared__ char smem[];
    const uint32_t sbase = smem_u32(smem);
    const int tid  = threadIdx.x;
    const int lane = tid & 31, wid = tid >> 5;
    const int warp_m = wid >> 2, warp_n = wid & 3;
    const int m0 = blockIdx.y << 7, n0 = blockIdx.x << 7;

    const int crow = tid >> 3, cq = tid & 7;

    const __half* Ab = Ag + (size_t)m0*KDIM;
    const __half* Wb = Wg + (size_t)n0*KDIM;

#define LOAD_STAGE(S, BUF) do {                                               \
    const uint32_t sa = sbase + (BUF)*STAGE_B;                                \
    const uint32_t sw = sa + STAGE_OPER;                                      \
    const size_t ko = (size_t)(S)*64 + cq*8;                                  \
    _Pragma("unroll")                                                         \
    for (int i_ = 0; i_ < 4; ++i_) {                                          \
        const int r_ = crow + 32*i_;                                          \
        cp16(sa + r_*GARS + cq*16, Ab + (size_t)r_*KDIM + ko);                \
        cp16(sw + r_*GARS + cq*16, Wb + (size_t)r_*KDIM + ko);                \
    }                                                                         \
} while (0)

    const uint32_t a_off = (uint32_t)((warp_m*64 + (lane & 15))*GARS
                                      + (lane >> 4)*16);
    const uint32_t b_off = (uint32_t)((warp_n*32 + (lane & 7)
                                      + ((lane >> 4) & 1)*8)*GARS
                                      + ((lane >> 3) & 1)*16);

    float acc[4][4][4] = {};

    LOAD_STAGE(0, 0); CP_COMMIT();
    LOAD_STAGE(1, 1); CP_COMMIT();

    for (int s = 0; s < NSTG; ++s) {
        CP_WAIT1();
        __syncthreads();
        if (s + 2 < NSTG) LOAD_STAGE(s + 2, (s + 2) % 3);
        CP_COMMIT();

        const uint32_t ab = sbase + (s % 3)*STAGE_B;
        const uint32_t bb = ab + STAGE_OPER;
#pragma unroll
        for (int kk = 0; kk < 4; ++kk) {
            uint32_t bf[2][4];
            ldsm4(bf[0], bb + b_off + kk*32);
            ldsm4(bf[1], bb + b_off + 16*GARS + kk*32);
#pragma unroll
            for (int mt = 0; mt < 4; ++mt) {
                uint32_t af[4];
                ldsm4(af, ab + a_off + mt*16*GARS + kk*32);
#pragma unroll
                for (int nt = 0; nt < 4; ++nt)
                    mma_h(acc[mt][nt], af[0], af[1], af[2], af[3],
                          bf[nt >> 1][(nt & 1)*2],
                          bf[nt >> 1][(nt & 1)*2 + 1]);
            }
        }
    }
#undef LOAD_STAGE

    const int gr = lane >> 2, tg = lane & 3;
#pragma unroll
    for (int mt = 0; mt < 4; ++mt) {
        const int r0 = m0 + warp_m*64 + mt*16 + gr;
#pragma unroll
        for (int nt = 0; nt < 4; ++nt) {
            const int col = n0 + warp_n*32 + nt*8 + tg*2;
            const float2 bv = *reinterpret_cast<const float2*>(bias + col);
            *reinterpret_cast<float2*>(&outp[(size_t)r0*DIM + col]) =
                make_float2(acc[mt][nt][0] + bv.x, acc[mt][nt][1] + bv.y);
            *reinterpret_cast<float2*>(&outp[(size_t)(r0+8)*DIM + col]) =
                make_float2(acc[mt][nt][2] + bv.x, acc[mt][nt][3] + bv.y);
        }
    }
}

// ---------------------------------------------------------------------------
// Tensor-core flash attention (fp16 mma.sync, fp32 softmax/accum) — R12 proven.
// ---------------------------------------------------------------------------
#define ARS        144
#define AQ_BYTES   (128*ARS)
#define AKV_BYTES  (128*ARS)
#define ATTN_SMEM  (AQ_BYTES + 4*AKV_BYTES)   // 92160
#define NSTG32     32

__global__ __launch_bounds__(256, 2)
void attn_mma()
{
    extern __shared__ char smem[];
    const uint32_t sb = smem_u32(smem);
    const int tid  = threadIdx.x;
    const int lane = tid & 31, wid = tid >> 5;
    const int bh = blockIdx.y;
    const int n0 = blockIdx.x << 7;

    const __half* Qg = g_qh + (size_t)bh * SEQ * DH;
    const __half* Kg = g_kh + (size_t)bh * SEQ * DH;
    const __half* Vg = g_vh + (size_t)bh * SEQ * DH;

    const int qr  = (lane & 7) + ((lane >> 3) & 1)*8;
    const int qc8 = ((lane >> 4) & 1)*8;
    const int kr  = (lane & 7) + ((lane >> 4) & 1)*8;
    const int kc8 = ((lane >> 3) & 1)*8;
    const int gid = lane >> 2, tg = lane & 3;
    const int i0 = wid*16;

    {
        const int crow = tid >> 3, cq = (tid & 7)*8;
#pragma unroll
        for (int i = 0; i < 4; ++i)
            cp16(sb + (crow + 32*i)*ARS + cq*2,
                 Qg + (size_t)(n0 + crow + 32*i)*DH + cq);
    }
    CP_COMMIT();

#define LOAD_KV(S, BUF) do {                                                  \
    const uint32_t kb = sb + AQ_BYTES + (BUF)*AKV_BYTES;                      \
    const int crow = tid >> 3, cq = (tid & 7)*8;                              \
    cp16(kb + crow*ARS + cq*2,        Kg + (size_t)((S)*64 + crow)*DH + cq);  \
    cp16(kb + (crow+32)*ARS + cq*2,   Kg + (size_t)((S)*64 + crow+32)*DH + cq);\
    cp16(kb + (crow+64)*ARS + cq*2,   Vg + (size_t)((S)*64 + crow)*DH + cq);  \
    cp16(kb + (crow+96)*ARS + cq*2,   Vg + (size_t)((S)*64 + crow+32)*DH + cq);\
} while (0)

    LOAD_KV(0, 0); CP_COMMIT();
    LOAD_KV(1, 1); CP_COMMIT();
    LOAD_KV(2, 2); CP_COMMIT();

    uint32_t qa[4][4];
    float oacc[8][4] = {};
    float m0r = -1e30f, m1r = -1e30f, l0r = 0.f, l1r = 0.f;

    for (int s = 0; s < NSTG32; ++s) {
        CP_WAIT_STAGE(s, NSTG32);
        __syncthreads();
        if (s == 0) {
#pragma unroll
            for (int t = 0; t < 4; ++t)
                ldsm4(qa[t], sb + (i0 + qr)*ARS + (16*t + qc8)*2);
        }
        if (s + 3 < NSTG32) LOAD_KV(s + 3, (s + 3) & 3);
        CP_COMMIT();

        const uint32_t kb = sb + AQ_BYTES + (s & 3)*AKV_BYTES;
        const uint32_t vb = kb + 64*ARS;

        float sacc[8][4] = {};
#pragma unroll
        for (int t = 0; t < 4; ++t) {
#pragma unroll
            for (int p = 0; p < 4; ++p) {
                uint32_t kf[4];
                ldsm4(kf, kb + (16*p + kr)*ARS + (16*t + kc8)*2);
                mma_h(sacc[2*p],   qa[t][0], qa[t][1], qa[t][2], qa[t][3],
                      kf[0], kf[1]);
                mma_h(sacc[2*p+1], qa[t][0], qa[t][1], qa[t][2], qa[t][3],
                      kf[2], kf[3]);
            }
        }

        float mx0 = -1e30f, mx1 = -1e30f;
#pragma unroll
        for (int nt = 0; nt < 8; ++nt) {
            mx0 = fmaxf(mx0, fmaxf(sacc[nt][0], sacc[nt][1]));
            mx1 = fmaxf(mx1, fmaxf(sacc[nt][2], sacc[nt][3]));
        }
        mx0 = fmaxf(mx0, __shfl_xor_sync(0xffffffffu, mx0, 1));
        mx0 = fmaxf(mx0, __shfl_xor_sync(0xffffffffu, mx0, 2));
        mx1 = fmaxf(mx1, __shfl_xor_sync(0xffffffffu, mx1, 1));
        mx1 = fmaxf(mx1, __shfl_xor_sync(0xffffffffu, mx1, 2));
        const float mn0 = fmaxf(m0r, mx0), mn1 = fmaxf(m1r, mx1);
        const float co0 = __expf(m0r - mn0), co1 = __expf(m1r - mn1);
        m0r = mn0; m1r = mn1;

        uint32_t ph0[8], ph1[8];
        float ps0 = 0.f, ps1 = 0.f;
#pragma unroll
        for (int nt = 0; nt < 8; ++nt) {
            float p0 = __expf(sacc[nt][0] - mn0);
            float p1 = __expf(sacc[nt][1] - mn0);
            float p2 = __expf(sacc[nt][2] - mn1);
            float p3 = __expf(sacc[nt][3] - mn1);
            ps0 += p0 + p1; ps1 += p2 + p3;
            __half2 h01 = __floats2half2_rn(p0, p1);
            __half2 h23 = __floats2half2_rn(p2, p3);
            ph0[nt] = *reinterpret_cast<uint32_t*>(&h01);
            ph1[nt] = *reinterpret_cast<uint32_t*>(&h23);
            oacc[nt][0] *= co0; oacc[nt][1] *= co0;
            oacc[nt][2] *= co1; oacc[nt][3] *= co1;
        }
        ps0 += __shfl_xor_sync(0xffffffffu, ps0, 1);
        ps0 += __shfl_xor_sync(0xffffffffu, ps0, 2);
        ps1 += __shfl_xor_sync(0xffffffffu, ps1, 1);
        ps1 += __shfl_xor_sync(0xffffffffu, ps1, 2);
        l0r = l0r*co0 + ps0;
        l1r = l1r*co1 + ps1;

#pragma unroll
        for (int t = 0; t < 4; ++t) {
            const uint32_t a0 = ph0[2*t],   a1 = ph1[2*t];
            const uint32_t a2 = ph0[2*t+1], a3 = ph1[2*t+1];
#pragma unroll
            for (int q = 0; q < 4; ++q) {
                uint32_t vf[4];
                ldsm4t(vf, vb + (16*t + qr)*ARS + (16*q + qc8)*2);
                mma_h(oacc[2*q],   a0, a1, a2, a3, vf[0], vf[1]);
                mma_h(oacc[2*q+1], a0, a1, a2, a3, vf[2], vf[3]);
            }
        }
    }
#undef LOAD_KV

    const int b = bh >> 4, h = bh & 15;
    const int n_r0 = n0 + i0 + gid;
    const size_t tok0 = (size_t)(b*SEQ + n_r0)*DIM;
    const size_t tok1 = (size_t)(b*SEQ + n_r0 + 8)*DIM;
    const float iv0 = 1.0f / l0r, iv1 = 1.0f / l1r;
#pragma unroll
    for (int nt = 0; nt < 8; ++nt) {
        const int c = h*64 + nt*8 + tg*2;
        *reinterpret_cast<__half2*>(&g_oh[tok0 + c]) =
            __floats2half2_rn(oacc[nt][0]*iv0, oacc[nt][1]*iv0);
        *reinterpret_cast<__half2*>(&g_oh[tok1 + c]) =
            __floats2half2_rn(oacc[nt][2]*iv1, oacc[nt][3]*iv1);
    }
}

// ---------------------------------------------------------------------------
extern "C" void kernel_launch(void* const* d_in, const int* in_sizes, int n_in,
                              void* d_out, int out_size)
{
    const float* x      = (const float*)d_in[0];
    const float* qkv_w  = (const float*)d_in[1];
    const float* qkv_b  = (const float*)d_in[2];
    const float* proj_w = (const float*)d_in[3];
    const float* proj_b = (const float*)d_in[4];
    float* out = (float*)d_out;

    cudaFuncSetAttribute(attn_mma, cudaFuncAttributeMaxDynamicSharedMemorySize,
                         ATTN_SMEM);
    cudaFuncSetAttribute(gemm_qkv, cudaFuncAttributeMaxDynamicSharedMemorySize,
                         QSMEM);
    cudaFuncSetAttribute(gemm_proj,
                         cudaFuncAttributeMaxDynamicSharedMemorySize, GSMEM);

    __half *xh_p, *oh_p, *qw_p, *pw_p;
    cudaGetSymbolAddress((void**)&xh_p, g_xh);
    cudaGetSymbolAddress((void**)&oh_p, g_oh);
    cudaGetSymbolAddress((void**)&qw_p, g_qkvwh);
    cudaGetSymbolAddress((void**)&pw_p, g_projwh);

    dim3 blk(256);

    // 1) fp32 -> fp16 converts (single fused launch)
    tofp16_all<<<NALL4/256, blk>>>(x, qkv_w, proj_w);

    // 2) QKV projection (occupancy-3 variant, fixed loads) -> fp16 q/k/v
    gemm_qkv<<<dim3(QKV_N/64, TOKENS/128), blk, QSMEM>>>(xh_p, qw_p, qkv_b);

    // 3) Tensor-core flash attention -> g_oh (fp16)
    attn_mma<<<dim3(SEQ/128, BATCH*NHEADS), blk, ATTN_SMEM>>>();

    // 4) Output projection (proven 128x128) -> d_out (fp32)
    gemm_proj<<<dim3(DIM/128, TOKENS/128), blk, GSMEM>>>(
        oh_p, pw_p, proj_b, out);
}